// round 9
// baseline (speedup 1.0000x reference)
#include <cuda_runtime.h>
#include <cuda_fp16.h>
#include <cstdint>
#include <math.h>

// Problem constants
#define B_   8
#define S_   1024      // H*W
#define E_   256
#define CS_  128
#define CT_  256
#define NH_  8
#define HD_  32

// ---------------- scratch (static device memory; no allocations) ----------------
__device__ uint32_t g_Wq_t [E_ * E_];        // tf32 bits of in_proj_w[:E]
__device__ uint32_t g_Wk2_t[E_ * CS_];       // tf32 bits of Wk @ kv_w
__device__ uint32_t g_Wv2_t[E_ * CS_];       // tf32 bits of Wv @ kv_w
__device__ uint32_t g_Mw_t [CT_ * E_];       // tf32 bits of fuse_w @ out_proj_w
__device__ float    g_fb   [CT_];            // fuse_w @ out_proj_b
__device__ uint32_t g_Q  [B_ * NH_ * S_ * HD_]; // tf32 bits, [b][h][s][d]
__device__ uint32_t g_K  [B_ * NH_ * S_ * HD_];
__device__ uint32_t g_V  [B_ * NH_ * S_ * HD_];
__device__ float    g_ctx[B_ * S_ * E_];        // [b][s][e] fp32

// ---------------- tf32 helpers ----------------
__device__ __forceinline__ uint32_t f2tf32(float x) {
    uint32_t r;
    asm("cvt.rna.tf32.f32 %0, %1;" : "=r"(r) : "f"(x));
    return r;
}
__device__ __forceinline__ void mma_tf32(float d[4], const uint32_t a[4],
                                         const uint32_t b[2], const float c[4]) {
    asm volatile(
        "mma.sync.aligned.m16n8k8.row.col.f32.tf32.tf32.f32 "
        "{%0,%1,%2,%3}, {%4,%5,%6,%7}, {%8,%9}, {%10,%11,%12,%13};"
        : "=f"(d[0]), "=f"(d[1]), "=f"(d[2]), "=f"(d[3])
        : "r"(a[0]), "r"(a[1]), "r"(a[2]), "r"(a[3]),
          "r"(b[0]), "r"(b[1]),
          "f"(c[0]), "f"(c[1]), "f"(c[2]), "f"(c[3]));
}

// ---------------- kernel 0: fold weight chains -> tf32 bits, zero attn map ----------------
__global__ void k_combine(const float* __restrict__ in_proj_w,
                          const float* __restrict__ kv_w,
                          const float* __restrict__ fuse_w,
                          const float* __restrict__ out_proj_w,
                          const float* __restrict__ out_proj_b,
                          float* __restrict__ out_attn) {
    int idx = blockIdx.x * blockDim.x + threadIdx.x;
    const int N1 = E_ * CS_;          // 32768  Wk2
    const int N2 = 2 * N1;            // 65536  Wv2
    const int N3 = N2 + CT_ * E_;     // 131072 Mw
    const int N4 = N3 + CT_;          // 131328 fb
    const int N5 = N4 + E_ * E_;      // 196864 Wq bits
    const int N6 = N5 + B_ * S_;      // 205056 attn zero
    if (idx < N1) {
        int f = idx / CS_, c = idx % CS_;
        float s = 0.f;
        for (int e = 0; e < E_; e++)
            s += in_proj_w[(E_ + f) * E_ + e] * kv_w[e * CS_ + c];
        g_Wk2_t[idx] = f2tf32(s);
    } else if (idx < N2) {
        int j = idx - N1;
        int f = j / CS_, c = j % CS_;
        float s = 0.f;
        for (int e = 0; e < E_; e++)
            s += in_proj_w[(2 * E_ + f) * E_ + e] * kv_w[e * CS_ + c];
        g_Wv2_t[j] = f2tf32(s);
    } else if (idx < N3) {
        int j = idx - N2;
        int cc = j / E_, ep = j % E_;
        float s = 0.f;
        for (int e = 0; e < E_; e++)
            s += fuse_w[cc * E_ + e] * out_proj_w[e * E_ + ep];
        g_Mw_t[j] = f2tf32(s);
    } else if (idx < N4) {
        int cc = idx - N3;
        float s = 0.f;
        for (int e = 0; e < E_; e++)
            s += fuse_w[cc * E_ + e] * out_proj_b[e];
        g_fb[cc] = s;
    } else if (idx < N5) {
        int j = idx - N4;
        g_Wq_t[j] = f2tf32(in_proj_w[j]);
    } else if (idx < N6) {
        out_attn[idx - N5] = 0.f;
    }
}

// ---------------- kernel 1: Q/K/V projection, tf32 MMA (merged 3-way) ----------------
// blockIdx.z: which = z>>3 (0=Q,1=K,2=V), b = z&7
__global__ void __launch_bounds__(256) k_proj(const float* __restrict__ tgt,
                                              const float* __restrict__ src,
                                              const float* __restrict__ in_proj_b) {
    __shared__ uint32_t As[32 * 68];   // [c][s] tf32 bits
    __shared__ uint32_t Bs[64 * 36];   // [e][c] tf32 bits
    int which = blockIdx.z >> 3;
    int b = blockIdx.z & 7;
    const uint32_t* W = (which == 0) ? g_Wq_t : (which == 1 ? g_Wk2_t : g_Wv2_t);
    uint32_t* Out = (which == 0) ? g_Q : (which == 1 ? g_K : g_V);
    const float* In = (which == 0) ? tgt : src;
    const float* bias = in_proj_b + which * E_;
    int Cin = (which == 0) ? CT_ : CS_;

    int s0 = blockIdx.x * 64, e0 = blockIdx.y * 64;
    int tid = threadIdx.x;
    int lane = tid & 31, w = tid >> 5;
    int gid = lane >> 2, tig = lane & 3;
    int mw = w >> 1, nh = w & 1;   // s block of 16, e half of 32
    const float* Ab = In + (size_t)b * Cin * S_;

    int sl = tid & 63, cl0 = tid >> 6;    // A loader coords
    int clB = tid & 31, el0 = tid >> 5;   // B loader coords

    float acc[4][4] = {};
    int nchunks = Cin >> 5;
    for (int ch = 0; ch < nchunks; ch++) {
        int c0 = ch << 5;
        __syncthreads();
        #pragma unroll
        for (int r = 0; r < 8; r++) {
            int cl = cl0 + 4 * r;
            As[cl * 68 + sl] = f2tf32(Ab[(size_t)(c0 + cl) * S_ + s0 + sl]);
        }
        #pragma unroll
        for (int r = 0; r < 8; r++) {
            int el = el0 + 8 * r;
            Bs[el * 36 + clB] = W[(size_t)(e0 + el) * Cin + c0 + clB];
        }
        __syncthreads();
        #pragma unroll
        for (int ks = 0; ks < 4; ks++) {
            uint32_t a[4];
            int sr = 16 * mw + gid;
            int cc = 8 * ks + tig;
            a[0] = As[cc * 68 + sr];
            a[1] = As[cc * 68 + sr + 8];
            a[2] = As[(cc + 4) * 68 + sr];
            a[3] = As[(cc + 4) * 68 + sr + 8];
            #pragma unroll
            for (int nt = 0; nt < 4; nt++) {
                uint32_t bb[2];
                int er = 32 * nh + 8 * nt + gid;
                bb[0] = Bs[er * 36 + 8 * ks + tig];
                bb[1] = Bs[er * 36 + 8 * ks + tig + 4];
                mma_tf32(acc[nt], a, bb, acc[nt]);
            }
        }
    }
    // epilogue: +bias, cvt to tf32 bits, store pairs
    #pragma unroll
    for (int nt = 0; nt < 4; nt++) {
        int e = e0 + 32 * nh + 8 * nt + 2 * tig;
        float b0 = bias[e], b1 = bias[e + 1];
        int h = e >> 5, d = e & 31;
        int s = s0 + 16 * mw + gid;
        uint32_t lo, hi;
        size_t base = (((size_t)(b * NH_ + h) * S_ + s) << 5) + d;
        lo = f2tf32(acc[nt][0] + b0); hi = f2tf32(acc[nt][1] + b1);
        *reinterpret_cast<uint2*>(&Out[base]) = make_uint2(lo, hi);
        lo = f2tf32(acc[nt][2] + b0); hi = f2tf32(acc[nt][3] + b1);
        *reinterpret_cast<uint2*>(&Out[base + (8u << 5)]) = make_uint2(lo, hi);
    }
}

// ---------------- kernel 2: fused attention, two-pass recompute ----------------
// Pass 1: S = QK^T (tf32 MMA) -> exp -> row sums l.
// Pass 2: recompute S, normalize e by 1/l in epilogue, write tf32 Et,
//         O += Et_norm @ V (already normalized), colsum via shuffles+smem.
// smem (word offsets):
//   Qs @0     [64][36] | Ks @2304 [64][36] | Vs @4608 [64][40]
//   Et @7168  [64][68] | lsum @11520 [64] | linv @11584 [64] | colsum @11648 [1024]
// total = 12672 words = 50688 bytes; no forced min-blocks (avoid spill forcing),
// HW can still co-schedule 2-3 CTAs/SM by regs+smem.
__global__ void __launch_bounds__(256, 2) k_attn(float* __restrict__ out_attn) {
    extern __shared__ uint32_t sm[];
    uint32_t* Qs = sm;
    uint32_t* Ks = sm + 2304;
    uint32_t* Vs = sm + 4608;
    uint32_t* Et = sm + 7168;
    float* lsum   = (float*)(sm + 11520);
    float* linv   = (float*)(sm + 11584);
    float* colsum = (float*)(sm + 11648);

    int bh = blockIdx.y;
    int b = bh >> 3, h = bh & 7;
    int q0 = blockIdx.x * 64;
    const uint32_t* Qb = g_Q + (size_t)bh * S_ * HD_;
    const uint32_t* Kb = g_K + (size_t)bh * S_ * HD_;
    const uint32_t* Vb = g_V + (size_t)bh * S_ * HD_;
    int tid = threadIdx.x;
    int lane = tid & 31, w = tid >> 5;
    int gid = lane >> 2, tig = lane & 3;
    int r8 = tid >> 5, d32 = tid & 31;

    int mw = w >> 1, nh = w & 1;   // S phase: q block 16, k half 32
    int mo = w & 3, no = w >> 2;   // O phase: q block 16, d half 16

    if (tid < 64) lsum[tid] = 0.f;
    #pragma unroll
    for (int r = 0; r < 4; r++) colsum[tid + 256 * r] = 0.f;

    #pragma unroll
    for (int r = 0; r < 8; r++) {
        int q = r8 + 8 * r;
        Qs[q * 36 + d32] = Qb[(size_t)(q0 + q) * HD_ + d32];
    }
    __syncthreads();

    // Q fragments, register-resident for both passes
    uint32_t aq[4][4];
    #pragma unroll
    for (int ks = 0; ks < 4; ks++) {
        int qr = 16 * mw + gid;
        int c  = ks * 8 + tig;
        aq[ks][0] = Qs[qr * 36 + c];
        aq[ks][1] = Qs[(qr + 8) * 36 + c];
        aq[ks][2] = Qs[qr * 36 + c + 4];
        aq[ks][3] = Qs[(qr + 8) * 36 + c + 4];
    }

    const float scale = 0.17677669529663687f; // 1/sqrt(32)

    // =================== PASS 1: row sums only ===================
    float l0 = 0.f, l1 = 0.f;
    for (int t = 0; t < 16; t++) {
        int k0 = t * 64;
        __syncthreads();   // prev S phase done reading Ks
        #pragma unroll
        for (int r = 0; r < 8; r++) {
            int k = r8 + 8 * r;
            Ks[k * 36 + d32] = Kb[(size_t)(k0 + k) * HD_ + d32];
        }
        __syncthreads();
        float sacc[4][4] = {};
        #pragma unroll
        for (int ks = 0; ks < 4; ks++) {
            #pragma unroll
            for (int nt = 0; nt < 4; nt++) {
                uint32_t bf[2];
                int key = 32 * nh + 8 * nt + gid;
                int d0  = ks * 8 + tig;
                bf[0] = Ks[key * 36 + d0];
                bf[1] = Ks[key * 36 + d0 + 4];
                mma_tf32(sacc[nt], aq[ks], bf, sacc[nt]);
            }
        }
        #pragma unroll
        for (int nt = 0; nt < 4; nt++) {
            l0 += __expf(sacc[nt][0] * scale) + __expf(sacc[nt][1] * scale);
            l1 += __expf(sacc[nt][2] * scale) + __expf(sacc[nt][3] * scale);
        }
    }
    __syncthreads();
    atomicAdd(&lsum[16 * mw + gid], l0);
    atomicAdd(&lsum[16 * mw + gid + 8], l1);
    __syncthreads();
    if (tid < 64) linv[tid] = 1.0f / lsum[tid];
    __syncthreads();

    // =================== PASS 2: normalized e -> O, colsum ===================
    float li0 = linv[16 * mw + gid];
    float li1 = linv[16 * mw + gid + 8];
    float oacc[2][4] = {};

    for (int t = 0; t < 16; t++) {
        int k0 = t * 64;
        __syncthreads();   // prev O phase done with Ks/Vs/Et
        #pragma unroll
        for (int r = 0; r < 8; r++) {
            int k = r8 + 8 * r;
            Ks[k * 36 + d32] = Kb[(size_t)(k0 + k) * HD_ + d32];
            Vs[k * 40 + d32] = Vb[(size_t)(k0 + k) * HD_ + d32];
        }
        __syncthreads();

        // ---- S phase (recompute)
        float sacc[4][4] = {};
        #pragma unroll
        for (int ks = 0; ks < 4; ks++) {
            #pragma unroll
            for (int nt = 0; nt < 4; nt++) {
                uint32_t bf[2];
                int key = 32 * nh + 8 * nt + gid;
                int d0  = ks * 8 + tig;
                bf[0] = Ks[key * 36 + d0];
                bf[1] = Ks[key * 36 + d0 + 4];
                mma_tf32(sacc[nt], aq[ks], bf, sacc[nt]);
            }
        }

        // ---- epilogue: normalized e -> Et bits, colsum reduction
        int qr = 16 * mw + gid;
        #pragma unroll
        for (int nt = 0; nt < 4; nt++) {
            float e0 = __expf(sacc[nt][0] * scale) * li0;
            float e1 = __expf(sacc[nt][1] * scale) * li0;
            float e2 = __expf(sacc[nt][2] * scale) * li1;
            float e3 = __expf(sacc[nt][3] * scale) * li1;
            int kloc = 32 * nh + 8 * nt + 2 * tig;
            *reinterpret_cast<uint2*>(&Et[qr * 68 + kloc]) =
                make_uint2(f2tf32(e0), f2tf32(e1));
            *reinterpret_cast<uint2*>(&Et[(qr + 8) * 68 + kloc]) =
                make_uint2(f2tf32(e2), f2tf32(e3));
            // column partial sums over this warp's 16 q rows
            float c0 = e0 + e2, c1 = e1 + e3;
            #pragma unroll
            for (int m = 4; m <= 16; m <<= 1) {
                c0 += __shfl_xor_sync(0xffffffffu, c0, m);
                c1 += __shfl_xor_sync(0xffffffffu, c1, m);
            }
            if (gid == 0) {
                atomicAdd(&colsum[k0 + kloc], c0);
                atomicAdd(&colsum[k0 + kloc + 1], c1);
            }
        }
        __syncthreads();

        // ---- O phase: O += Et_norm(64x64) @ Vs(64x32)
        #pragma unroll
        for (int ks = 0; ks < 8; ks++) {
            uint32_t ae[4];
            int qo = 16 * mo + gid;
            int c0i = 8 * ks + tig;
            ae[0] = Et[qo * 68 + c0i];
            ae[1] = Et[(qo + 8) * 68 + c0i];
            ae[2] = Et[qo * 68 + c0i + 4];
            ae[3] = Et[(qo + 8) * 68 + c0i + 4];
            #pragma unroll
            for (int j = 0; j < 2; j++) {
                uint32_t bv[2];
                int dcol = 16 * no + 8 * j + gid;
                int krow = 8 * ks + tig;
                bv[0] = Vs[krow * 40 + dcol];
                bv[1] = Vs[(krow + 4) * 40 + dcol];
                mma_tf32(oacc[j], ae, bv, oacc[j]);
            }
        }
    }

    // ---- context (already normalized)
    {
        int qr = 16 * mo + gid;
        #pragma unroll
        for (int j = 0; j < 2; j++) {
            int d = 16 * no + 8 * j + 2 * tig;
            *reinterpret_cast<float2*>(
                &g_ctx[((size_t)b * S_ + q0 + qr) * E_ + h * HD_ + d]) =
                make_float2(oacc[j][0], oacc[j][1]);
            *reinterpret_cast<float2*>(
                &g_ctx[((size_t)b * S_ + q0 + qr + 8) * E_ + h * HD_ + d]) =
                make_float2(oacc[j][2], oacc[j][3]);
        }
    }

    // ---- flush colsum to attn map
    __syncthreads();
    const float sc = 1.0f / 8192.0f;
    #pragma unroll
    for (int r = 0; r < 4; r++) {
        int k = tid + 256 * r;
        atomicAdd(&out_attn[b * S_ + k], colsum[k] * sc);
    }
}

// ---------------- kernel 3: fuse + BN + SiLU + residual, tf32 MMA ----------------
__global__ void __launch_bounds__(256) k_fuse(const float* __restrict__ tgt,
                       const float* __restrict__ gamma,
                       const float* __restrict__ beta,
                       const float* __restrict__ mean,
                       const float* __restrict__ var,
                       float* __restrict__ out) {
    __shared__ uint32_t As[64 * 36];  // Mw bits [c][e-chunk]
    __shared__ uint32_t Bs[64 * 36];  // ctx bits [s][e-chunk]
    int b = blockIdx.z;
    int c0 = blockIdx.x * 64, s0 = blockIdx.y * 64;
    const float* Cb = g_ctx + (size_t)b * S_ * E_;
    int tid = threadIdx.x;
    int lane = tid & 31, w = tid >> 5;
    int gid = lane >> 2, tig = lane & 3;
    int mw = w >> 1, nh = w & 1;   // c block of 16, s half of 32
    int el = tid & 31, rl0 = tid >> 5;

    float acc[4][4] = {};
    #pragma unroll 1
    for (int ch = 0; ch < 8; ch++) {
        int e0 = ch << 5;
        __syncthreads();
        #pragma unroll
        for (int r = 0; r < 8; r++) {
            int row = rl0 + 8 * r;
            As[row * 36 + el] = g_Mw_t[(size_t)(c0 + row) * E_ + e0 + el];
            Bs[row * 36 + el] = f2tf32(Cb[(size_t)(s0 + row) * E_ + e0 + el]);
        }
        __syncthreads();
        #pragma unroll
        for (int ks = 0; ks < 4; ks++) {
            uint32_t a[4];
            int cr = 16 * mw + gid;
            int ec = 8 * ks + tig;
            a[0] = As[cr * 36 + ec];
            a[1] = As[(cr + 8) * 36 + ec];
            a[2] = As[cr * 36 + ec + 4];
            a[3] = As[(cr + 8) * 36 + ec + 4];
            #pragma unroll
            for (int nt = 0; nt < 4; nt++) {
                uint32_t bb[2];
                int sr = 32 * nh + 8 * nt + gid;
                bb[0] = Bs[sr * 36 + ec];
                bb[1] = Bs[sr * 36 + ec + 4];
                mma_tf32(acc[nt], a, bb, acc[nt]);
            }
        }
    }
    // epilogue: BN + SiLU + residual
    int c = c0 + 16 * mw + gid;
    float inv0 = gamma[c] * rsqrtf(var[c] + 1e-5f);
    float mu0 = mean[c], bet0 = beta[c], fb0 = g_fb[c];
    float inv1 = gamma[c + 8] * rsqrtf(var[c + 8] + 1e-5f);
    float mu1 = mean[c + 8], bet1 = beta[c + 8], fb1 = g_fb[c + 8];
    #pragma unroll
    for (int nt = 0; nt < 4; nt++) {
        int s = s0 + 32 * nh + 8 * nt + 2 * tig;
        size_t off0 = (size_t)b * (CT_ * S_) + (size_t)c * S_ + s;
        size_t off1 = off0 + (size_t)8 * S_;
        float2 t0 = *reinterpret_cast<const float2*>(&tgt[off0]);
        float2 t1 = *reinterpret_cast<const float2*>(&tgt[off1]);
        float bn, sg;
        float2 y0, y1;
        bn = (acc[nt][0] + fb0 - mu0) * inv0 + bet0;
        sg = 1.0f / (1.0f + __expf(-bn)); y0.x = t0.x + bn * sg;
        bn = (acc[nt][1] + fb0 - mu0) * inv0 + bet0;
        sg = 1.0f / (1.0f + __expf(-bn)); y0.y = t0.y + bn * sg;
        bn = (acc[nt][2] + fb1 - mu1) * inv1 + bet1;
        sg = 1.0f / (1.0f + __expf(-bn)); y1.x = t1.x + bn * sg;
        bn = (acc[nt][3] + fb1 - mu1) * inv1 + bet1;
        sg = 1.0f / (1.0f + __expf(-bn)); y1.y = t1.y + bn * sg;
        *reinterpret_cast<float2*>(&out[off0]) = y0;
        *reinterpret_cast<float2*>(&out[off1]) = y1;
    }
}

// ---------------- host launch ----------------
extern "C" void kernel_launch(void* const* d_in, const int* in_sizes, int n_in,
                              void* d_out, int out_size) {
    const float* tgt        = (const float*)d_in[0];
    const float* src        = (const float*)d_in[1];
    const float* kv_w       = (const float*)d_in[2];
    const float* in_proj_w  = (const float*)d_in[3];
    const float* in_proj_b  = (const float*)d_in[4];
    const float* out_proj_w = (const float*)d_in[5];
    const float* out_proj_b = (const float*)d_in[6];
    const float* fuse_w     = (const float*)d_in[7];
    const float* bn_gamma   = (const float*)d_in[8];
    const float* bn_beta    = (const float*)d_in[9];
    const float* bn_mean    = (const float*)d_in[10];
    const float* bn_var     = (const float*)d_in[11];

    float* out_y    = (float*)d_out;                         // B*Ct*H*W
    float* out_attn = (float*)d_out + (size_t)B_ * CT_ * S_; // B*H*W

    static const int ATTN_SMEM = 50688;
    cudaFuncSetAttribute(k_attn, cudaFuncAttributeMaxDynamicSharedMemorySize, ATTN_SMEM);

    // 0. fold weights -> tf32 bit matrices, zero attn map
    k_combine<<<(205056 + 255) / 256, 256>>>(in_proj_w, kv_w, fuse_w,
                                             out_proj_w, out_proj_b, out_attn);

    // 1. Q/K/V projections in one launch (tf32 MMA)
    dim3 gp(S_ / 64, E_ / 64, 3 * B_);
    k_proj<<<gp, 256>>>(tgt, src, in_proj_b);

    // 2. fused two-pass tensor-core attention
    dim3 ga(S_ / 64, B_ * NH_);
    k_attn<<<ga, 256, ATTN_SMEM>>>(out_attn);

    // 3. fuse + BN + SiLU + residual (tf32 MMA)
    dim3 gf(CT_ / 64, S_ / 64, B_);
    k_fuse<<<gf, 256>>>(tgt, bn_gamma, bn_beta, bn_mean, bn_var, out_y);
}